// round 10
// baseline (speedup 1.0000x reference)
#include <cuda_runtime.h>
#include <math.h>

#define Nn 256
#define Cc 100
#define Dd 512
#define RW (Nn + Cc)      // 356 rows (proxies first, then X)
#define GB 256            // grid; 2 CTAs/SM co-resident (b and b+148 share an SM)
#define RPAD 384          // padded rows in partial buffers
#define NT 18             // GEMM output tiles after symmetry pruning
#define SK 8              // split-K factor (K-slice = 64)
#define NORMB 45          // norm blocks
#define LOG2E 1.442695040888963f

typedef unsigned long long ull;

// 18 needed 64x64 tiles of the [384,256] output (rows: 100 IP + 256 G):
// lower-triangle G tiles that the loss never reads are skipped.
__constant__ unsigned char c_tr[NT] = {0,0,0,0, 1,1,1,1, 2,2,2,2, 3,3,3, 4,4, 5};
__constant__ unsigned char c_tc[NT] = {0,1,2,3, 0,1,2,3, 0,1,2,3, 1,2,3, 2,3, 3};

// ---------------- scratch (device globals; no allocation allowed) -------------
__device__ float  g_part[SK][RPAD * Nn]; // raw split-K partials
__device__ float  g_rinv[RW];            // 1/max(||row||,eps)
__device__ float  g_Out[RW * Nn];        // scaled: rows 0..99 IPt[c][i]; 100..355 G[i][j]
__device__ float  g_partF[GB];
__device__ int    g_partI[GB];
__device__ unsigned g_tileCnt[NT];       // split-K arrival counters (reset each launch)
__device__ unsigned g_normCnt = 0;       // norm-block completion counter
__device__ unsigned g_barCount = 0;
__device__ unsigned g_barGen   = 0;
__device__ unsigned g_done     = 0;

__device__ __forceinline__ float ex2f(float x) {
    float r; asm("ex2.approx.ftz.f32 %0, %1;" : "=f"(r) : "f"(x)); return r;
}
__device__ __forceinline__ ull pack2(float x, float y) {
    ull r; asm("mov.b64 %0, {%1, %2};" : "=l"(r) : "f"(x), "f"(y)); return r;
}
__device__ __forceinline__ void unpack2(float& x, float& y, ull v) {
    asm("mov.b64 {%0, %1}, %2;" : "=f"(x), "=f"(y) : "l"(v));
}
__device__ __forceinline__ ull fma2(ull a, ull b, ull c) {
    ull d; asm("fma.rn.f32x2 %0, %1, %2, %3;" : "=l"(d) : "l"(a), "l"(b), "l"(c));
    return d;
}

// ---------------- software grid barrier (all GB blocks co-resident) ----------
__device__ __forceinline__ void grid_barrier() {
    __syncthreads();
    __threadfence();
    if (threadIdx.x == 0) {
        unsigned oldgen = *(volatile unsigned*)&g_barGen;
        unsigned ticket = atomicAdd(&g_barCount, 1u);
        if (ticket == GB - 1) {
            g_barCount = 0;
            __threadfence();
            atomicExch(&g_barGen, oldgen + 1u);
        } else {
            while (*(volatile unsigned*)&g_barGen == oldgen) { __nanosleep(64); }
        }
        __threadfence();
    }
    __syncthreads();
}

__device__ __forceinline__ float clip1(float x) { return fminf(fmaxf(x, -1.f), 1.f); }

// ---------------- fused kernel ------------------------------------------------
__global__ void __launch_bounds__(256, 2)
k_fused(const float* __restrict__ X, const float* __restrict__ P,
        const int* __restrict__ T, float* __restrict__ out) {
    int tid  = threadIdx.x;    // 256
    int b    = blockIdx.x;     // 0..255
    int lane = tid & 31;
    int wid  = tid >> 5;       // 0..7

    __shared__ float As[32][64];     // transposed + XOR-swizzled: As[k][row ^ (k&24)]
    __shared__ float Bs[32][64];
    __shared__ float shIp1[Cc];
    __shared__ int   shT[Nn];
    __shared__ float sred[8];
    __shared__ int   sredi[8];
    __shared__ int   lastFlag;
    __shared__ int   isRed;

    shT[tid] = T[tid];               // prefetch labels (used after the barrier)

    // ===== Phase 1a: split-K GEMM + inline per-tile reduce (blocks 0..143) =====
    // 18 tiles (64x64) x 8 K-slices of 64.  part[ks][r][j] = W_r[Ks].X_j[Ks]
    if (b < NT * SK) {
        int ks = b & 7;
        int t  = b >> 3;
        int trow = c_tr[t] * 64;
        int tcol = c_tc[t] * 64;
        int kb   = ks * 64;

        int rowL = tid >> 2;           // 0..63 (load row)
        int kq   = tid & 3;            // 0..3
        int sb   = kq * 8;             // kk base within chunk
        int colS = rowL ^ sb;          // swizzled store column ((sb+j)&24 == sb)
        int ga   = trow + rowL;
        const float* Arow = (ga < Cc) ? (P + ga * Dd)
                          : (ga < RW) ? (X + (ga - Cc) * Dd) : (const float*)0;
        const float* Brow = X + (tcol + rowL) * Dd;

        int ty = tid >> 4, tx = tid & 15;   // compute coords: rows 4ty.., cols 4tx..

        ull acc2[4][2];                     // packed fp32x2 accumulators
        #pragma unroll
        for (int i = 0; i < 4; i++) { acc2[i][0] = 0ull; acc2[i][1] = 0ull; }

        float4 pa0, pa1, pb0, pb1;
        {
            int k0 = kb + sb;
            pa0 = Arow ? *(const float4*)(Arow + k0)     : make_float4(0,0,0,0);
            pa1 = Arow ? *(const float4*)(Arow + k0 + 4) : make_float4(0,0,0,0);
            pb0 = *(const float4*)(Brow + k0);
            pb1 = *(const float4*)(Brow + k0 + 4);
        }

        #pragma unroll
        for (int ch = 0; ch < 2; ch++) {
            As[sb+0][colS]=pa0.x; As[sb+1][colS]=pa0.y; As[sb+2][colS]=pa0.z; As[sb+3][colS]=pa0.w;
            As[sb+4][colS]=pa1.x; As[sb+5][colS]=pa1.y; As[sb+6][colS]=pa1.z; As[sb+7][colS]=pa1.w;
            Bs[sb+0][colS]=pb0.x; Bs[sb+1][colS]=pb0.y; Bs[sb+2][colS]=pb0.z; Bs[sb+3][colS]=pb0.w;
            Bs[sb+4][colS]=pb1.x; Bs[sb+5][colS]=pb1.y; Bs[sb+6][colS]=pb1.z; Bs[sb+7][colS]=pb1.w;
            __syncthreads();

            if (ch < 1) {
                int k0 = kb + 32 + sb;
                pa0 = Arow ? *(const float4*)(Arow + k0)     : make_float4(0,0,0,0);
                pa1 = Arow ? *(const float4*)(Arow + k0 + 4) : make_float4(0,0,0,0);
                pb0 = *(const float4*)(Brow + k0);
                pb1 = *(const float4*)(Brow + k0 + 4);
            }

            #pragma unroll
            for (int kk = 0; kk < 32; kk++) {
                float4 a = *(const float4*)&As[kk][(4 * ty) ^ (kk & 24)];
                float4 v = *(const float4*)&Bs[kk][(4 * tx) ^ (kk & 24)];
                ull b01 = pack2(v.x, v.y);
                ull b23 = pack2(v.z, v.w);
                ull a0 = pack2(a.x, a.x);
                ull a1 = pack2(a.y, a.y);
                ull a2 = pack2(a.z, a.z);
                ull a3 = pack2(a.w, a.w);
                acc2[0][0] = fma2(a0, b01, acc2[0][0]); acc2[0][1] = fma2(a0, b23, acc2[0][1]);
                acc2[1][0] = fma2(a1, b01, acc2[1][0]); acc2[1][1] = fma2(a1, b23, acc2[1][1]);
                acc2[2][0] = fma2(a2, b01, acc2[2][0]); acc2[2][1] = fma2(a2, b23, acc2[2][1]);
                acc2[3][0] = fma2(a3, b01, acc2[3][0]); acc2[3][1] = fma2(a3, b23, acc2[3][1]);
            }
            __syncthreads();
        }

        // raw store to partial buffer
        float* Pt = g_part[ks];
        #pragma unroll
        for (int i = 0; i < 4; i++) {
            float4 o4;
            unpack2(o4.x, o4.y, acc2[i][0]);
            unpack2(o4.z, o4.w, acc2[i][1]);
            int r = trow + 4 * ty + i;
            *(float4*)&Pt[r * Nn + tcol + 4 * tx] = o4;
        }

        // ---- last-arriving split-K block reduces + scales this tile ----------
        if (tid == 0) {
            __threadfence();
            unsigned tt = atomicAdd(&g_tileCnt[t], 1u);
            isRed = (tt == SK - 1);
        }
        __syncthreads();
        if (isRed) {
            if (tid == 0) {   // norms finish far earlier; spin is ~never taken
                while (*(volatile unsigned*)&g_normCnt < NORMB) { __nanosleep(32); }
            }
            __syncthreads();
            #pragma unroll
            for (int q = 0; q < 4; q++) {
                int idx = tid * 4 + q;            // float4 slot within 64x64 tile
                int r   = idx >> 4;               // 0..63
                int c4  = idx & 15;               // 0..15
                int gr  = trow + r;
                if (gr < RW) {
                    int o = gr * (Nn / 4) + (tcol >> 2) + c4;
                    float4 sv = make_float4(0.f, 0.f, 0.f, 0.f);
                    #pragma unroll
                    for (int p = 0; p < SK; p++) {
                        float4 sq = __ldcg(&((const float4*)g_part[p])[o]);
                        sv.x += sq.x; sv.y += sq.y; sv.z += sq.z; sv.w += sq.w;
                    }
                    int cb = tcol + 4 * c4;
                    float4 rc = *(const float4*)&g_rinv[Cc + cb];
                    float sc = 9.0f * g_rinv[gr];
                    float4 ov;
                    ov.x = sv.x * sc * rc.x;
                    ov.y = sv.y * sc * rc.y;
                    ov.z = sv.z * sc * rc.z;
                    ov.w = sv.w * sc * rc.w;
                    ((float4*)g_Out)[o] = ov;
                }
            }
        }
    }
    // ===== Phase 1b: row norms (blocks 144..188, concurrent with GEMM) =========
    else if (b < 144 + NORMB) {
        int row = (b - 144) * 8 + wid;           // 45 blocks x 8 warps = 360 >= 356
        if (row < RW) {
            const float* rp = (row < Cc) ? (P + row * Dd) : (X + (row - Cc) * Dd);
            const float4* rp4 = (const float4*)rp;
            float s = 0.f;
            #pragma unroll
            for (int m = 0; m < 4; m++) {
                float4 v = rp4[lane + 32 * m];
                s += v.x * v.x + v.y * v.y + v.z * v.z + v.w * v.w;
            }
            #pragma unroll
            for (int o = 16; o; o >>= 1) s += __shfl_xor_sync(0xffffffffu, s, o);
            if (lane == 0) g_rinv[row] = 1.0f / fmaxf(sqrtf(s), 1e-12f);
        }
        __syncthreads();
        if (tid == 0) { __threadfence(); atomicAdd(&g_normCnt, 1u); }
    }

    grid_barrier();   // single global sync: all tiles reduced into g_Out

    // ===== Phase 2: losses. Scaled norms^2 == 9; bias = 18 ======================
    // Job permutation balances co-resident blocks (b and b+148 share an SM):
    //   b==108          -> real-sample job (single-resident SM)
    //   b in 109..147   -> i1 = b-109  (np 255..217; single-resident SMs)
    //   b in 0..107     -> i1 = 39+b   (np 216-b)   } pair sums to 217
    //   b in 148..255   -> i1 = 402-b  (np b-147)   }
    int job = (b == 108) ? -1
            : (b > 108)  ? ((b < 148) ? (b - 109) : (402 - b))
                         : (39 + b);

    float myLoss = 0.f;
    int   myCnt  = 0;

    if (job < 0) {
        // real-sample loss: one thread per row i.  d_c = 18 - 2*ip_c
        int i = tid;
        int ti = shT[i];
        const float tl = 2.0f * LOG2E;
        const float nb = -18.0f * LOG2E;
        float s = 0.f;
        float pre[10];
        #pragma unroll
        for (int u = 0; u < 10; u++) pre[u] = g_Out[u * Nn + i];
        for (int cb = 0; cb < Cc; cb += 10) {
            float cur[10];
            #pragma unroll
            for (int u = 0; u < 10; u++) cur[u] = pre[u];
            if (cb < 90) {
                #pragma unroll
                for (int u = 0; u < 10; u++) pre[u] = g_Out[(cb + 10 + u) * Nn + i];
            }
            #pragma unroll
            for (int u = 0; u < 10; u++)
                s += ex2f(fmaf(tl, cur[u], nb));
        }
        float dT = fmaxf(fmaf(-2.f, g_Out[ti * Nn + i], 18.0f), 0.f);
        myLoss = dT + __logf(s);
    } else {
        // pair loss: i1 = job; each thread covers TWO i2 (aligned)
        int i1 = job;
        if (tid < Cc) shIp1[tid] = g_Out[tid * Nn + i1];
        __syncthreads();
        int e0  = (i1 + 1) & ~1;                 // even start (first slot may be masked)
        int nth = (Nn - e0) >> 1;                // threads with work (<=128)
        if (tid < nth) {
            int i2 = e0 + 2 * tid;               // handles i2 and i2+1
            int c1 = shT[i1];
            int c2a = shT[i2], c2b = shT[i2 + 1];
            bool va = (i2 > i1) && (c2a != c1);
            bool vb = (c2b != c1);
            float x1p1 = clip1(shIp1[c1]);
            float2 ggp = *(const float2*)&g_Out[(Cc + i1) * Nn + i2];
            float2 xc1 = *(const float2*)&g_Out[c1 * Nn + i2];
            int   c2v[2]   = { c2a, c2b };
            bool  vv[2]    = { va, vb };
            float ggv[2]   = { ggp.x, ggp.y };
            float x2p1i[2] = { xc1.x, xc1.y };
            float x2p2i[2], tla[2], tlb[2], lamv[2], lmv[2], t2v[2];
            #pragma unroll
            for (int k = 0; k < 2; k++) {
                x2p2i[k] = g_Out[c2v[k] * Nn + i2 + k];
                float x1p2 = clip1(shIp1[c2v[k]]);
                float x2p1 = clip1(x2p1i[k]);
                float x2p2 = clip1(x2p2i[k]);
                float num = x2p2 - x2p1;
                float den = num + x1p1 - x1p2;
                float lam = vv[k] ? fminf(fmaxf(num / den, 0.3f), 0.7f) : 0.5f;
                float lm  = 1.f - lam;
                float nw2 = 9.0f * (lam * lam + lm * lm) + 2.f * lam * lm * ggv[k];
                float t2  = 6.0f / fmaxf(sqrtf(nw2), 1e-12f);
                lamv[k] = lam; lmv[k] = lm; t2v[k] = t2;
                tla[k] = t2 * LOG2E * lam;       // coeff on shIp1
                tlb[k] = t2 * LOG2E * lm;        // coeff on ip(i2)
            }
            const float nb = -18.0f * LOG2E;
            float s0 = 0.f, s1 = 0.f;
            float2 pre[10];
            #pragma unroll
            for (int u = 0; u < 10; u++) pre[u] = *(const float2*)&g_Out[u * Nn + i2];
            for (int cb = 0; cb < Cc; cb += 10) {
                float2 cur[10];
                #pragma unroll
                for (int u = 0; u < 10; u++) cur[u] = pre[u];
                if (cb < 90) {
                    #pragma unroll
                    for (int u = 0; u < 10; u++)
                        pre[u] = *(const float2*)&g_Out[(cb + 10 + u) * Nn + i2];
                }
                #pragma unroll
                for (int u = 0; u < 10; u++) {
                    float sh = shIp1[cb + u];
                    s0 += ex2f(fmaf(tla[0], sh, fmaf(tlb[0], cur[u].x, nb)));
                    s1 += ex2f(fmaf(tla[1], sh, fmaf(tlb[1], cur[u].y, nb)));
                }
            }
            float sv2[2] = { s0, s1 };
            #pragma unroll
            for (int k = 0; k < 2; k++) {
                if (vv[k]) {
                    float dc1 = fmaxf(fmaf(-t2v[k],
                                 fmaf(lamv[k], shIp1[c1] - x2p1i[k], x2p1i[k]), 18.0f), 0.f);
                    float dc2 = fmaxf(fmaf(-t2v[k],
                                 fmaf(lamv[k], shIp1[c2v[k]] - x2p2i[k], x2p2i[k]), 18.0f), 0.f);
                    myLoss += lamv[k] * dc1 + lmv[k] * dc2 + __logf(sv2[k]);
                    myCnt++;
                }
            }
        }
    }

    // block reduce: warp shuffle + one smem hop
    #pragma unroll
    for (int o = 16; o; o >>= 1) {
        myLoss += __shfl_xor_sync(0xffffffffu, myLoss, o);
        myCnt  += __shfl_xor_sync(0xffffffffu, myCnt,  o);
    }
    if (lane == 0) { sred[wid] = myLoss; sredi[wid] = myCnt; }
    __syncthreads();

    // ===== Phase 3: partial store + ticket; last block reduces in parallel =====
    if (tid == 0) {
        float fs = sred[0]+sred[1]+sred[2]+sred[3]+sred[4]+sred[5]+sred[6]+sred[7];
        int   is = sredi[0]+sredi[1]+sredi[2]+sredi[3]+sredi[4]+sredi[5]+sredi[6]+sredi[7];
        g_partF[b] = fs;
        g_partI[b] = is;
        __threadfence();
        unsigned t = atomicAdd(&g_done, 1u);
        lastFlag = (t == GB - 1);
    }
    __syncthreads();
    if (lastFlag) {
        float fv = __ldcg(&g_partF[tid]);     // bypass L1 (written by other SMs)
        int   iv = __ldcg(&g_partI[tid]);
        #pragma unroll
        for (int o = 16; o; o >>= 1) {
            fv += __shfl_xor_sync(0xffffffffu, fv, o);
            iv += __shfl_xor_sync(0xffffffffu, iv, o);
        }
        if (lane == 0) { sred[wid] = fv; sredi[wid] = iv; }
        __syncthreads();
        // reset per-launch counters for graph replay (no other block touches
        // them after its phase-4 ticket, and all tickets precede lastFlag)
        if (tid < NT) g_tileCnt[tid] = 0u;
        if (tid == NT) g_normCnt = 0u;
        if (tid == 0) {
            float fs = sred[0]+sred[1]+sred[2]+sred[3]+sred[4]+sred[5]+sred[6]+sred[7];
            int   is = sredi[0]+sredi[1]+sredi[2]+sredi[3]+sredi[4]+sredi[5]+sredi[6]+sredi[7];
            out[0] = fs / (float)(Nn + is);
            __threadfence();
            atomicExch(&g_done, 0u);          // reset for graph replay
        }
    }
}

// ---------------- entry -------------------------------------------------------
extern "C" void kernel_launch(void* const* d_in, const int* in_sizes, int n_in,
                              void* d_out, int out_size) {
    const float* X = (const float*)d_in[0];   // [256,512]
    const float* P = (const float*)d_in[1];   // [100,512]
    const int*   T = (const int*)d_in[2];     // [256]
    float* out = (float*)d_out;

    k_fused<<<GB, 256>>>(X, P, T, out);
}

// round 11
// speedup vs baseline: 1.2100x; 1.2100x over previous
#include <cuda_runtime.h>
#include <math.h>

#define Nn 256
#define Cc 100
#define Dd 512
#define RW (Nn + Cc)      // 356 rows (proxies first, then X)
#define GB 256            // grid; 2 CTAs/SM co-resident (b and b+148 share an SM)
#define RPAD 384          // padded rows in partial buffers
#define NT 18             // GEMM output tiles after symmetry pruning
#define SK 8              // split-K factor (K-slice = 64)
#define NRED 108          // reducer blocks (144..251), 6 per tile
#define SEG 171           // float4 slots per reducer block (6*171 >= 1024)
#define LOG2E 1.442695040888963f

typedef unsigned long long ull;

// 18 needed 64x64 tiles of the [384,256] output (rows: 100 IP + 256 G):
// lower-triangle G tiles that the loss never reads are skipped.
__constant__ unsigned char c_tr[NT] = {0,0,0,0, 1,1,1,1, 2,2,2,2, 3,3,3, 4,4, 5};
__constant__ unsigned char c_tc[NT] = {0,1,2,3, 0,1,2,3, 0,1,2,3, 1,2,3, 2,3, 3};

// ---------------- scratch (device globals; no allocation allowed) -------------
__device__ float  g_part[SK][RPAD * Nn]; // raw split-K partials
__device__ float  g_rinv[RW];            // 1/max(||row||,eps)
__device__ float  g_Out[RW * Nn];        // scaled: rows 0..99 IPt[c][i]; 100..355 G[i][j]
__device__ float  g_partF[GB];
__device__ int    g_partI[GB];
__device__ unsigned g_tileCnt[NT];       // split-K arrival counters (reset each launch)
__device__ unsigned g_normCnt = 0;       // norm completion counter (reset each launch)
__device__ unsigned g_barCount = 0;
__device__ unsigned g_barGen   = 0;
__device__ unsigned g_done     = 0;

__device__ __forceinline__ float ex2f(float x) {
    float r; asm("ex2.approx.ftz.f32 %0, %1;" : "=f"(r) : "f"(x)); return r;
}
__device__ __forceinline__ ull pack2(float x, float y) {
    ull r; asm("mov.b64 %0, {%1, %2};" : "=l"(r) : "f"(x), "f"(y)); return r;
}
__device__ __forceinline__ void unpack2(float& x, float& y, ull v) {
    asm("mov.b64 {%0, %1}, %2;" : "=f"(x), "=f"(y) : "l"(v));
}
__device__ __forceinline__ ull fma2(ull a, ull b, ull c) {
    ull d; asm("fma.rn.f32x2 %0, %1, %2, %3;" : "=l"(d) : "l"(a), "l"(b), "l"(c));
    return d;
}

// ---------------- software grid barrier (all GB blocks co-resident) ----------
__device__ __forceinline__ void grid_barrier() {
    __syncthreads();
    __threadfence();
    if (threadIdx.x == 0) {
        unsigned oldgen = *(volatile unsigned*)&g_barGen;
        unsigned ticket = atomicAdd(&g_barCount, 1u);
        if (ticket == GB - 1) {
            g_barCount = 0;
            __threadfence();
            atomicExch(&g_barGen, oldgen + 1u);
        } else {
            while (*(volatile unsigned*)&g_barGen == oldgen) { }
        }
        __threadfence();
    }
    __syncthreads();
}

__device__ __forceinline__ float clip1(float x) { return fminf(fmaxf(x, -1.f), 1.f); }

// ---------------- fused kernel ------------------------------------------------
__global__ void __launch_bounds__(256, 2)
k_fused(const float* __restrict__ X, const float* __restrict__ P,
        const int* __restrict__ T, float* __restrict__ out) {
    int tid  = threadIdx.x;    // 256
    int b    = blockIdx.x;     // 0..255
    int lane = tid & 31;
    int wid  = tid >> 5;       // 0..7

    __shared__ float As[32][64];     // transposed + XOR-swizzled: As[k][row ^ (k&24)]
    __shared__ float Bs[32][64];
    __shared__ float shIp1[Cc];
    __shared__ int   shT[Nn];
    __shared__ float sred[8];
    __shared__ int   sredi[8];
    __shared__ int   lastFlag;

    shT[tid] = T[tid];               // prefetch labels (used after the barrier)

    // ===== Phase 1a: split-K GEMM (blocks 0..143) — pure GEMM ==================
    // 18 tiles (64x64) x 8 K-slices of 64.  part[ks][r][j] = W_r[Ks].X_j[Ks]
    if (b < NT * SK) {
        int ks = b & 7;
        int t  = b >> 3;
        int trow = c_tr[t] * 64;
        int tcol = c_tc[t] * 64;
        int kb   = ks * 64;

        int rowL = tid >> 2;           // 0..63 (load row)
        int kq   = tid & 3;            // 0..3
        int sb   = kq * 8;             // kk base within chunk
        int colS = rowL ^ sb;          // swizzled store column ((sb+j)&24 == sb)
        int ga   = trow + rowL;
        const float* Arow = (ga < Cc) ? (P + ga * Dd)
                          : (ga < RW) ? (X + (ga - Cc) * Dd) : (const float*)0;
        const float* Brow = X + (tcol + rowL) * Dd;

        int ty = tid >> 4, tx = tid & 15;   // compute coords: rows 4ty.., cols 4tx..

        ull acc2[4][2];                     // packed fp32x2 accumulators
        #pragma unroll
        for (int i = 0; i < 4; i++) { acc2[i][0] = 0ull; acc2[i][1] = 0ull; }

        float4 pa0, pa1, pb0, pb1;
        {
            int k0 = kb + sb;
            pa0 = Arow ? *(const float4*)(Arow + k0)     : make_float4(0,0,0,0);
            pa1 = Arow ? *(const float4*)(Arow + k0 + 4) : make_float4(0,0,0,0);
            pb0 = *(const float4*)(Brow + k0);
            pb1 = *(const float4*)(Brow + k0 + 4);
        }

        #pragma unroll
        for (int ch = 0; ch < 2; ch++) {
            As[sb+0][colS]=pa0.x; As[sb+1][colS]=pa0.y; As[sb+2][colS]=pa0.z; As[sb+3][colS]=pa0.w;
            As[sb+4][colS]=pa1.x; As[sb+5][colS]=pa1.y; As[sb+6][colS]=pa1.z; As[sb+7][colS]=pa1.w;
            Bs[sb+0][colS]=pb0.x; Bs[sb+1][colS]=pb0.y; Bs[sb+2][colS]=pb0.z; Bs[sb+3][colS]=pb0.w;
            Bs[sb+4][colS]=pb1.x; Bs[sb+5][colS]=pb1.y; Bs[sb+6][colS]=pb1.z; Bs[sb+7][colS]=pb1.w;
            __syncthreads();

            if (ch < 1) {
                int k0 = kb + 32 + sb;
                pa0 = Arow ? *(const float4*)(Arow + k0)     : make_float4(0,0,0,0);
                pa1 = Arow ? *(const float4*)(Arow + k0 + 4) : make_float4(0,0,0,0);
                pb0 = *(const float4*)(Brow + k0);
                pb1 = *(const float4*)(Brow + k0 + 4);
            }

            #pragma unroll
            for (int kk = 0; kk < 32; kk++) {
                float4 a = *(const float4*)&As[kk][(4 * ty) ^ (kk & 24)];
                float4 v = *(const float4*)&Bs[kk][(4 * tx) ^ (kk & 24)];
                ull b01 = pack2(v.x, v.y);
                ull b23 = pack2(v.z, v.w);
                ull a0 = pack2(a.x, a.x);
                ull a1 = pack2(a.y, a.y);
                ull a2 = pack2(a.z, a.z);
                ull a3 = pack2(a.w, a.w);
                acc2[0][0] = fma2(a0, b01, acc2[0][0]); acc2[0][1] = fma2(a0, b23, acc2[0][1]);
                acc2[1][0] = fma2(a1, b01, acc2[1][0]); acc2[1][1] = fma2(a1, b23, acc2[1][1]);
                acc2[2][0] = fma2(a2, b01, acc2[2][0]); acc2[2][1] = fma2(a2, b23, acc2[2][1]);
                acc2[3][0] = fma2(a3, b01, acc2[3][0]); acc2[3][1] = fma2(a3, b23, acc2[3][1]);
            }
            __syncthreads();
        }

        // raw store to partial buffer, then signal tile arrival
        float* Pt = g_part[ks];
        #pragma unroll
        for (int i = 0; i < 4; i++) {
            float4 o4;
            unpack2(o4.x, o4.y, acc2[i][0]);
            unpack2(o4.z, o4.w, acc2[i][1]);
            int r = trow + 4 * ty + i;
            *(float4*)&Pt[r * Nn + tcol + 4 * tx] = o4;
        }
        __syncthreads();
        if (tid == 0) {
            __threadfence();
            atomicAdd(&g_tileCnt[t], 1u);
        }
    }
    // ===== Phase 1b: reducers (blocks 144..251): norms, then per-tile reduce ===
    else if (b < 144 + NRED) {
        int rb = b - 144;                        // 0..107

        // --- row norms: 4 rows per block (warps 0..3); 108*4 = 432 >= 356
        if (wid < 4) {
            int row = rb * 4 + wid;
            if (row < RW) {
                const float* rp = (row < Cc) ? (P + row * Dd) : (X + (row - Cc) * Dd);
                const float4* rp4 = (const float4*)rp;
                float s = 0.f;
                #pragma unroll
                for (int m = 0; m < 4; m++) {
                    float4 v = rp4[lane + 32 * m];
                    s += v.x * v.x + v.y * v.y + v.z * v.z + v.w * v.w;
                }
                #pragma unroll
                for (int o = 16; o; o >>= 1) s += __shfl_xor_sync(0xffffffffu, s, o);
                if (lane == 0) g_rinv[row] = 1.0f / fmaxf(sqrtf(s), 1e-12f);
            }
        }
        __syncthreads();
        if (tid == 0) { __threadfence(); atomicAdd(&g_normCnt, 1u); }

        // --- wait for all norms + this tile's 8 split-K partials, then reduce
        int t    = rb / 6;                       // tile 0..17
        int seg  = rb % 6;                       // segment within tile
        int trow = c_tr[t] * 64;
        int tcol = c_tc[t] * 64;
        if (tid == 0) {
            while (*(volatile unsigned*)&g_normCnt < NRED)      { __nanosleep(32); }
            while (*(volatile unsigned*)&g_tileCnt[t] < SK)     { __nanosleep(32); }
        }
        __syncthreads();

        int slot = seg * SEG + tid;              // float4 slot within 64x64 tile
        int hi   = min((seg + 1) * SEG, 1024);
        if (slot < hi) {
            int r  = slot >> 4;                  // 0..63
            int c4 = slot & 15;                  // 0..15
            int gr = trow + r;
            if (gr < RW) {
                int o = gr * (Nn / 4) + (tcol >> 2) + c4;
                float4 sv = make_float4(0.f, 0.f, 0.f, 0.f);
                #pragma unroll
                for (int p = 0; p < SK; p++) {
                    float4 sq = __ldcg(&((const float4*)g_part[p])[o]);
                    sv.x += sq.x; sv.y += sq.y; sv.z += sq.z; sv.w += sq.w;
                }
                int cb = tcol + 4 * c4;
                float4 rc;
                rc.x = __ldcg(&g_rinv[Cc + cb]);
                rc.y = __ldcg(&g_rinv[Cc + cb + 1]);
                rc.z = __ldcg(&g_rinv[Cc + cb + 2]);
                rc.w = __ldcg(&g_rinv[Cc + cb + 3]);
                float sc = 9.0f * __ldcg(&g_rinv[gr]);
                float4 ov;
                ov.x = sv.x * sc * rc.x;
                ov.y = sv.y * sc * rc.y;
                ov.z = sv.z * sc * rc.z;
                ov.w = sv.w * sc * rc.w;
                ((float4*)g_Out)[o] = ov;
            }
        }
    }
    // blocks 252..255: nothing in phase 1

    grid_barrier();   // single global sync: g_Out complete

    // ===== Phase 2: losses. Scaled norms^2 == 9; bias = 18 ======================
    // Job permutation balances co-resident blocks (b and b+148 share an SM):
    //   b==108          -> real-sample job (single-resident SM)
    //   b in 109..147   -> i1 = b-109  (np 255..217; single-resident SMs)
    //   b in 0..107     -> i1 = 39+b   (np 216-b)   } pair sums to 217
    //   b in 148..255   -> i1 = 402-b  (np b-147)   }
    int job = (b == 108) ? -1
            : (b > 108)  ? ((b < 148) ? (b - 109) : (402 - b))
                         : (39 + b);

    float myLoss = 0.f;
    int   myCnt  = 0;

    if (job < 0) {
        // real-sample loss: one thread per row i.  d_c = 18 - 2*ip_c
        int i = tid;
        int ti = shT[i];
        const float tl = 2.0f * LOG2E;
        const float nb = -18.0f * LOG2E;
        float s = 0.f;
        float pre[10];
        #pragma unroll
        for (int u = 0; u < 10; u++) pre[u] = g_Out[u * Nn + i];
        for (int cb = 0; cb < Cc; cb += 10) {
            float cur[10];
            #pragma unroll
            for (int u = 0; u < 10; u++) cur[u] = pre[u];
            if (cb < 90) {
                #pragma unroll
                for (int u = 0; u < 10; u++) pre[u] = g_Out[(cb + 10 + u) * Nn + i];
            }
            #pragma unroll
            for (int u = 0; u < 10; u++)
                s += ex2f(fmaf(tl, cur[u], nb));
        }
        float dT = fmaxf(fmaf(-2.f, g_Out[ti * Nn + i], 18.0f), 0.f);
        myLoss = dT + __logf(s);
    } else {
        // pair loss: i1 = job; each thread covers TWO i2 (aligned)
        int i1 = job;
        if (tid < Cc) shIp1[tid] = g_Out[tid * Nn + i1];
        __syncthreads();
        int e0  = (i1 + 1) & ~1;                 // even start (first slot may be masked)
        int nth = (Nn - e0) >> 1;                // threads with work (<=128)
        if (tid < nth) {
            int i2 = e0 + 2 * tid;               // handles i2 and i2+1
            int c1 = shT[i1];
            int c2a = shT[i2], c2b = shT[i2 + 1];
            bool va = (i2 > i1) && (c2a != c1);
            bool vb = (c2b != c1);
            float x1p1 = clip1(shIp1[c1]);
            float2 ggp = *(const float2*)&g_Out[(Cc + i1) * Nn + i2];
            float2 xc1 = *(const float2*)&g_Out[c1 * Nn + i2];
            int   c2v[2]   = { c2a, c2b };
            bool  vv[2]    = { va, vb };
            float ggv[2]   = { ggp.x, ggp.y };
            float x2p1i[2] = { xc1.x, xc1.y };
            float x2p2i[2], tla[2], tlb[2], lamv[2], lmv[2], t2v[2];
            #pragma unroll
            for (int k = 0; k < 2; k++) {
                x2p2i[k] = g_Out[c2v[k] * Nn + i2 + k];
                float x1p2 = clip1(shIp1[c2v[k]]);
                float x2p1 = clip1(x2p1i[k]);
                float x2p2 = clip1(x2p2i[k]);
                float num = x2p2 - x2p1;
                float den = num + x1p1 - x1p2;
                float lam = vv[k] ? fminf(fmaxf(num / den, 0.3f), 0.7f) : 0.5f;
                float lm  = 1.f - lam;
                float nw2 = 9.0f * (lam * lam + lm * lm) + 2.f * lam * lm * ggv[k];
                float t2  = 6.0f / fmaxf(sqrtf(nw2), 1e-12f);
                lamv[k] = lam; lmv[k] = lm; t2v[k] = t2;
                tla[k] = t2 * LOG2E * lam;       // coeff on shIp1
                tlb[k] = t2 * LOG2E * lm;        // coeff on ip(i2)
            }
            const float nb = -18.0f * LOG2E;
            float s0 = 0.f, s1 = 0.f;
            float2 pre[10];
            #pragma unroll
            for (int u = 0; u < 10; u++) pre[u] = *(const float2*)&g_Out[u * Nn + i2];
            for (int cb = 0; cb < Cc; cb += 10) {
                float2 cur[10];
                #pragma unroll
                for (int u = 0; u < 10; u++) cur[u] = pre[u];
                if (cb < 90) {
                    #pragma unroll
                    for (int u = 0; u < 10; u++)
                        pre[u] = *(const float2*)&g_Out[(cb + 10 + u) * Nn + i2];
                }
                #pragma unroll
                for (int u = 0; u < 10; u++) {
                    float sh = shIp1[cb + u];
                    s0 += ex2f(fmaf(tla[0], sh, fmaf(tlb[0], cur[u].x, nb)));
                    s1 += ex2f(fmaf(tla[1], sh, fmaf(tlb[1], cur[u].y, nb)));
                }
            }
            float sv2[2] = { s0, s1 };
            #pragma unroll
            for (int k = 0; k < 2; k++) {
                if (vv[k]) {
                    float dc1 = fmaxf(fmaf(-t2v[k],
                                 fmaf(lamv[k], shIp1[c1] - x2p1i[k], x2p1i[k]), 18.0f), 0.f);
                    float dc2 = fmaxf(fmaf(-t2v[k],
                                 fmaf(lamv[k], shIp1[c2v[k]] - x2p2i[k], x2p2i[k]), 18.0f), 0.f);
                    myLoss += lamv[k] * dc1 + lmv[k] * dc2 + __logf(sv2[k]);
                    myCnt++;
                }
            }
        }
    }

    // block reduce: warp shuffle + one smem hop
    #pragma unroll
    for (int o = 16; o; o >>= 1) {
        myLoss += __shfl_xor_sync(0xffffffffu, myLoss, o);
        myCnt  += __shfl_xor_sync(0xffffffffu, myCnt,  o);
    }
    if (lane == 0) { sred[wid] = myLoss; sredi[wid] = myCnt; }
    __syncthreads();

    // ===== Phase 3: partial store + ticket; last block reduces in parallel =====
    if (tid == 0) {
        float fs = sred[0]+sred[1]+sred[2]+sred[3]+sred[4]+sred[5]+sred[6]+sred[7];
        int   is = sredi[0]+sredi[1]+sredi[2]+sredi[3]+sredi[4]+sredi[5]+sredi[6]+sredi[7];
        g_partF[b] = fs;
        g_partI[b] = is;
        __threadfence();
        unsigned t = atomicAdd(&g_done, 1u);
        lastFlag = (t == GB - 1);
    }
    __syncthreads();
    if (lastFlag) {
        float fv = __ldcg(&g_partF[tid]);     // bypass L1 (written by other SMs)
        int   iv = __ldcg(&g_partI[tid]);
        #pragma unroll
        for (int o = 16; o; o >>= 1) {
            fv += __shfl_xor_sync(0xffffffffu, fv, o);
            iv += __shfl_xor_sync(0xffffffffu, iv, o);
        }
        if (lane == 0) { sred[wid] = fv; sredi[wid] = iv; }
        __syncthreads();
        // reset per-launch counters for graph replay (all blocks have passed
        // their use of these counters before the last ticket arrives)
        if (tid < NT) g_tileCnt[tid] = 0u;
        if (tid == NT) g_normCnt = 0u;
        if (tid == 0) {
            float fs = sred[0]+sred[1]+sred[2]+sred[3]+sred[4]+sred[5]+sred[6]+sred[7];
            int   is = sredi[0]+sredi[1]+sredi[2]+sredi[3]+sredi[4]+sredi[5]+sredi[6]+sredi[7];
            out[0] = fs / (float)(Nn + is);
            __threadfence();
            atomicExch(&g_done, 0u);          // reset for graph replay
        }
    }
}

// ---------------- entry -------------------------------------------------------
extern "C" void kernel_launch(void* const* d_in, const int* in_sizes, int n_in,
                              void* d_out, int out_size) {
    const float* X = (const float*)d_in[0];   // [256,512]
    const float* P = (const float*)d_in[1];   // [100,512]
    const int*   T = (const int*)d_in[2];     // [256]
    float* out = (float*)d_out;

    k_fused<<<GB, 256>>>(X, P, T, out);
}

// round 12
// speedup vs baseline: 1.3776x; 1.1385x over previous
#include <cuda_runtime.h>
#include <math.h>

#define Nn 256
#define Cc 100
#define Dd 512
#define RW (Nn + Cc)      // 356 rows (proxies first, then X)
#define GB 256            // grid; 2 CTAs/SM co-resident (b and b+148 share an SM)
#define RPAD 384          // padded rows in partial buffers
#define NT 18             // GEMM output tiles after symmetry pruning
#define SK 8              // split-K factor (K-slice = 64)
#define NRED 108          // reducer blocks (144..251), 6 per tile
#define SEG 171           // float4 slots per reducer block (6*171 >= 1024)
#define LOG2E 1.442695040888963f

typedef unsigned long long ull;

// 18 needed 64x64 tiles of the [384,256] output (rows: 100 IP + 256 G):
// lower-triangle G tiles that the loss never reads are skipped.
__constant__ unsigned char c_tr[NT] = {0,0,0,0, 1,1,1,1, 2,2,2,2, 3,3,3, 4,4, 5};
__constant__ unsigned char c_tc[NT] = {0,1,2,3, 0,1,2,3, 0,1,2,3, 1,2,3, 2,3, 3};

// ---------------- scratch (device globals; no allocation allowed) -------------
__device__ float  g_part[SK][RPAD * Nn]; // raw split-K partials
__device__ float  g_rinv[RW];            // 1/max(||row||,eps)
__device__ float  g_Out[RW * Nn];        // scaled: rows 0..99 IPt[c][i]; 100..355 G[i][j]
__device__ float  g_partF[GB];
__device__ int    g_partI[GB];
__device__ unsigned g_tileCnt[NT];       // split-K arrival counters (reset each launch)
__device__ unsigned g_normCnt = 0;       // norm completion counter
__device__ unsigned g_redCnt  = 0;       // reducer completion counter (release flag)
__device__ unsigned g_done    = 0;

__device__ __forceinline__ float ex2f(float x) {
    float r; asm("ex2.approx.ftz.f32 %0, %1;" : "=f"(r) : "f"(x)); return r;
}
__device__ __forceinline__ ull pack2(float x, float y) {
    ull r; asm("mov.b64 %0, {%1, %2};" : "=l"(r) : "f"(x), "f"(y)); return r;
}
__device__ __forceinline__ void unpack2(float& x, float& y, ull v) {
    asm("mov.b64 {%0, %1}, %2;" : "=f"(x), "=f"(y) : "l"(v));
}
__device__ __forceinline__ ull fma2(ull a, ull b, ull c) {
    ull d; asm("fma.rn.f32x2 %0, %1, %2, %3;" : "=l"(d) : "l"(a), "l"(b), "l"(c));
    return d;
}

__device__ __forceinline__ float clip1(float x) { return fminf(fmaxf(x, -1.f), 1.f); }

// ---------------- fused kernel ------------------------------------------------
__global__ void __launch_bounds__(256, 2)
k_fused(const float* __restrict__ X, const float* __restrict__ P,
        const int* __restrict__ T, float* __restrict__ out) {
    int tid  = threadIdx.x;    // 256
    int b    = blockIdx.x;     // 0..255
    int lane = tid & 31;
    int wid  = tid >> 5;       // 0..7

    __shared__ float As[32][64];     // transposed + XOR-swizzled: As[k][row ^ (k&24)]
    __shared__ float Bs[32][64];
    __shared__ float shIp1[Cc];
    __shared__ int   shT[Nn];
    __shared__ float shS0[128];      // high-half partial exp-sums
    __shared__ float shS1[128];
    __shared__ float sred[8];
    __shared__ int   sredi[8];
    __shared__ int   lastFlag;

    shT[tid] = T[tid];               // prefetch labels (used after release)

    // ===== Phase 1a: split-K GEMM (blocks 0..143) — pure GEMM ==================
    // 18 tiles (64x64) x 8 K-slices of 64.  part[ks][r][j] = W_r[Ks].X_j[Ks]
    if (b < NT * SK) {
        int ks = b & 7;
        int t  = b >> 3;
        int trow = c_tr[t] * 64;
        int tcol = c_tc[t] * 64;
        int kb   = ks * 64;

        int rowL = tid >> 2;           // 0..63 (load row)
        int kq   = tid & 3;            // 0..3
        int sb   = kq * 8;             // kk base within chunk
        int colS = rowL ^ sb;          // swizzled store column ((sb+j)&24 == sb)
        int ga   = trow + rowL;
        const float* Arow = (ga < Cc) ? (P + ga * Dd)
                          : (ga < RW) ? (X + (ga - Cc) * Dd) : (const float*)0;
        const float* Brow = X + (tcol + rowL) * Dd;

        int ty = tid >> 4, tx = tid & 15;   // compute coords: rows 4ty.., cols 4tx..

        ull acc2[4][2];                     // packed fp32x2 accumulators
        #pragma unroll
        for (int i = 0; i < 4; i++) { acc2[i][0] = 0ull; acc2[i][1] = 0ull; }

        float4 pa0, pa1, pb0, pb1;
        {
            int k0 = kb + sb;
            pa0 = Arow ? *(const float4*)(Arow + k0)     : make_float4(0,0,0,0);
            pa1 = Arow ? *(const float4*)(Arow + k0 + 4) : make_float4(0,0,0,0);
            pb0 = *(const float4*)(Brow + k0);
            pb1 = *(const float4*)(Brow + k0 + 4);
        }

        #pragma unroll
        for (int ch = 0; ch < 2; ch++) {
            As[sb+0][colS]=pa0.x; As[sb+1][colS]=pa0.y; As[sb+2][colS]=pa0.z; As[sb+3][colS]=pa0.w;
            As[sb+4][colS]=pa1.x; As[sb+5][colS]=pa1.y; As[sb+6][colS]=pa1.z; As[sb+7][colS]=pa1.w;
            Bs[sb+0][colS]=pb0.x; Bs[sb+1][colS]=pb0.y; Bs[sb+2][colS]=pb0.z; Bs[sb+3][colS]=pb0.w;
            Bs[sb+4][colS]=pb1.x; Bs[sb+5][colS]=pb1.y; Bs[sb+6][colS]=pb1.z; Bs[sb+7][colS]=pb1.w;
            __syncthreads();

            if (ch < 1) {
                int k0 = kb + 32 + sb;
                pa0 = Arow ? *(const float4*)(Arow + k0)     : make_float4(0,0,0,0);
                pa1 = Arow ? *(const float4*)(Arow + k0 + 4) : make_float4(0,0,0,0);
                pb0 = *(const float4*)(Brow + k0);
                pb1 = *(const float4*)(Brow + k0 + 4);
            }

            #pragma unroll
            for (int kk = 0; kk < 32; kk++) {
                float4 a = *(const float4*)&As[kk][(4 * ty) ^ (kk & 24)];
                float4 v = *(const float4*)&Bs[kk][(4 * tx) ^ (kk & 24)];
                ull b01 = pack2(v.x, v.y);
                ull b23 = pack2(v.z, v.w);
                ull a0 = pack2(a.x, a.x);
                ull a1 = pack2(a.y, a.y);
                ull a2 = pack2(a.z, a.z);
                ull a3 = pack2(a.w, a.w);
                acc2[0][0] = fma2(a0, b01, acc2[0][0]); acc2[0][1] = fma2(a0, b23, acc2[0][1]);
                acc2[1][0] = fma2(a1, b01, acc2[1][0]); acc2[1][1] = fma2(a1, b23, acc2[1][1]);
                acc2[2][0] = fma2(a2, b01, acc2[2][0]); acc2[2][1] = fma2(a2, b23, acc2[2][1]);
                acc2[3][0] = fma2(a3, b01, acc2[3][0]); acc2[3][1] = fma2(a3, b23, acc2[3][1]);
            }
            __syncthreads();
        }

        // raw store to partial buffer, then signal tile arrival
        float* Pt = g_part[ks];
        #pragma unroll
        for (int i = 0; i < 4; i++) {
            float4 o4;
            unpack2(o4.x, o4.y, acc2[i][0]);
            unpack2(o4.z, o4.w, acc2[i][1]);
            int r = trow + 4 * ty + i;
            *(float4*)&Pt[r * Nn + tcol + 4 * tx] = o4;
        }
        __syncthreads();
        if (tid == 0) {
            __threadfence();
            atomicAdd(&g_tileCnt[t], 1u);
        }
    }
    // ===== Phase 1b: reducers (blocks 144..251): norms, then per-tile reduce ===
    else if (b < 144 + NRED) {
        int rb = b - 144;                        // 0..107

        // --- row norms: 4 rows per block (warps 0..3); 108*4 = 432 >= 356
        if (wid < 4) {
            int row = rb * 4 + wid;
            if (row < RW) {
                const float* rp = (row < Cc) ? (P + row * Dd) : (X + (row - Cc) * Dd);
                const float4* rp4 = (const float4*)rp;
                float s = 0.f;
                #pragma unroll
                for (int m = 0; m < 4; m++) {
                    float4 v = rp4[lane + 32 * m];
                    s += v.x * v.x + v.y * v.y + v.z * v.z + v.w * v.w;
                }
                #pragma unroll
                for (int o = 16; o; o >>= 1) s += __shfl_xor_sync(0xffffffffu, s, o);
                if (lane == 0) g_rinv[row] = 1.0f / fmaxf(sqrtf(s), 1e-12f);
            }
        }
        __syncthreads();
        if (tid == 0) { __threadfence(); atomicAdd(&g_normCnt, 1u); }

        // --- wait for all norms + this tile's 8 split-K partials, then reduce
        int t    = rb / 6;                       // tile 0..17
        int seg  = rb % 6;                       // segment within tile
        int trow = c_tr[t] * 64;
        int tcol = c_tc[t] * 64;
        if (tid == 0) {
            while (*(volatile unsigned*)&g_normCnt < NRED)      { __nanosleep(32); }
            while (*(volatile unsigned*)&g_tileCnt[t] < SK)     { __nanosleep(32); }
        }
        __syncthreads();

        int slot = seg * SEG + tid;              // float4 slot within 64x64 tile
        int hi   = min((seg + 1) * SEG, 1024);
        if (slot < hi) {
            int r  = slot >> 4;                  // 0..63
            int c4 = slot & 15;                  // 0..15
            int gr = trow + r;
            if (gr < RW) {
                int o = gr * (Nn / 4) + (tcol >> 2) + c4;
                float4 sv = make_float4(0.f, 0.f, 0.f, 0.f);
                #pragma unroll
                for (int p = 0; p < SK; p++) {
                    float4 sq = __ldcg(&((const float4*)g_part[p])[o]);
                    sv.x += sq.x; sv.y += sq.y; sv.z += sq.z; sv.w += sq.w;
                }
                int cb = tcol + 4 * c4;
                float4 rc;
                rc.x = __ldcg(&g_rinv[Cc + cb]);
                rc.y = __ldcg(&g_rinv[Cc + cb + 1]);
                rc.z = __ldcg(&g_rinv[Cc + cb + 2]);
                rc.w = __ldcg(&g_rinv[Cc + cb + 3]);
                float sc = 9.0f * __ldcg(&g_rinv[gr]);
                float4 ov;
                ov.x = sv.x * sc * rc.x;
                ov.y = sv.y * sc * rc.y;
                ov.z = sv.z * sc * rc.z;
                ov.w = sv.w * sc * rc.w;
                ((float4*)g_Out)[o] = ov;
            }
        }

        // signal segment complete (release)
        __syncthreads();
        if (tid == 0) { __threadfence(); atomicAdd(&g_redCnt, 1u); }
    }
    // blocks 252..255: nothing in phase 1

    // ===== Release: wait for all 108 reducer segments (replaces grid barrier) ==
    if (tid == 0) {
        while (*(volatile unsigned*)&g_redCnt < NRED) { __nanosleep(32); }
        __threadfence();
    }
    __syncthreads();

    // ===== Phase 2: losses. Scaled norms^2 == 9; bias = 18 ======================
    // Job permutation balances co-resident blocks (b and b+148 share an SM):
    //   b==108          -> real-sample job (single-resident SM)
    //   b in 109..147   -> i1 = b-109  (np 255..217; single-resident SMs)
    //   b in 0..107     -> i1 = 39+b   (np 216-b)   } pair sums to 217
    //   b in 148..255   -> i1 = 402-b  (np b-147)   }
    int job = (b == 108) ? -1
            : (b > 108)  ? ((b < 148) ? (b - 109) : (402 - b))
                         : (39 + b);

    float myLoss = 0.f;
    int   myCnt  = 0;

    if (job < 0) {
        // real-sample loss: one thread per row i.  d_c = 18 - 2*ip_c
        int i = tid;
        int ti = shT[i];
        const float tl = 2.0f * LOG2E;
        const float nb = -18.0f * LOG2E;
        float s = 0.f;
        float pre[10];
        #pragma unroll
        for (int u = 0; u < 10; u++) pre[u] = g_Out[u * Nn + i];
        for (int cb = 0; cb < Cc; cb += 10) {
            float cur[10];
            #pragma unroll
            for (int u = 0; u < 10; u++) cur[u] = pre[u];
            if (cb < 90) {
                #pragma unroll
                for (int u = 0; u < 10; u++) pre[u] = g_Out[(cb + 10 + u) * Nn + i];
            }
            #pragma unroll
            for (int u = 0; u < 10; u++)
                s += ex2f(fmaf(tl, cur[u], nb));
        }
        float dT = fmaxf(fmaf(-2.f, g_Out[ti * Nn + i], 18.0f), 0.f);
        myLoss = dT + __logf(s);
    } else {
        // pair loss: i1 = job. Thread layout: pt = tid&127 indexes the pair-duo
        // (i2, i2+1); half = tid>>7 selects classes [0,50) or [50,100).
        // High half accumulates its exp-sums and hands them to the low half.
        int i1 = job;
        if (tid < Cc) shIp1[tid] = g_Out[tid * Nn + i1];
        __syncthreads();
        int e0   = (i1 + 1) & ~1;                // even start (first slot may be masked)
        int nth  = (Nn - e0) >> 1;               // pair-duo threads (<=128)
        int half = tid >> 7;                     // 0 or 1
        int pt   = tid & 127;
        float s0 = 0.f, s1 = 0.f;
        bool  vv[2] = { false, false };
        int   c2v[2];
        float x2p1i[2], x2p2i[2], lamv[2], lmv[2], t2v[2];
        int   c1 = shT[i1];
        if (pt < nth) {
            int i2 = e0 + 2 * pt;                // handles i2 and i2+1
            int c2a = shT[i2], c2b = shT[i2 + 1];
            vv[0] = (i2 > i1) && (c2a != c1);
            vv[1] = (c2b != c1);
            c2v[0] = c2a; c2v[1] = c2b;
            float x1p1 = clip1(shIp1[c1]);
            float2 ggp = *(const float2*)&g_Out[(Cc + i1) * Nn + i2];
            float2 xc1 = *(const float2*)&g_Out[c1 * Nn + i2];
            float ggv[2] = { ggp.x, ggp.y };
            x2p1i[0] = xc1.x; x2p1i[1] = xc1.y;
            float tla[2], tlb[2];
            #pragma unroll
            for (int k = 0; k < 2; k++) {
                x2p2i[k] = g_Out[c2v[k] * Nn + i2 + k];
                float x1p2 = clip1(shIp1[c2v[k]]);
                float x2p1 = clip1(x2p1i[k]);
                float x2p2 = clip1(x2p2i[k]);
                float num = x2p2 - x2p1;
                float den = num + x1p1 - x1p2;
                float lam = vv[k] ? fminf(fmaxf(num / den, 0.3f), 0.7f) : 0.5f;
                float lm  = 1.f - lam;
                float nw2 = 9.0f * (lam * lam + lm * lm) + 2.f * lam * lm * ggv[k];
                float t2  = 6.0f / fmaxf(sqrtf(nw2), 1e-12f);
                lamv[k] = lam; lmv[k] = lm; t2v[k] = t2;
                tla[k] = t2 * LOG2E * lam;       // coeff on shIp1
                tlb[k] = t2 * LOG2E * lm;        // coeff on ip(i2)
            }
            const float nb = -18.0f * LOG2E;
            int cbase = half * 50;               // this half's class range
            float2 pre[10];
            #pragma unroll
            for (int u = 0; u < 10; u++)
                pre[u] = *(const float2*)&g_Out[(cbase + u) * Nn + i2];
            #pragma unroll
            for (int blk = 0; blk < 5; blk++) {
                int cb = cbase + blk * 10;
                float2 cur[10];
                #pragma unroll
                for (int u = 0; u < 10; u++) cur[u] = pre[u];
                if (blk < 4) {
                    #pragma unroll
                    for (int u = 0; u < 10; u++)
                        pre[u] = *(const float2*)&g_Out[(cb + 10 + u) * Nn + i2];
                }
                #pragma unroll
                for (int u = 0; u < 10; u++) {
                    float sh = shIp1[cb + u];
                    s0 += ex2f(fmaf(tla[0], sh, fmaf(tlb[0], cur[u].x, nb)));
                    s1 += ex2f(fmaf(tla[1], sh, fmaf(tlb[1], cur[u].y, nb)));
                }
            }
            if (half) { shS0[pt] = s0; shS1[pt] = s1; }
        }
        __syncthreads();
        if (pt < nth && half == 0) {
            s0 += shS0[pt];
            s1 += shS1[pt];
            float sv2[2] = { s0, s1 };
            #pragma unroll
            for (int k = 0; k < 2; k++) {
                if (vv[k]) {
                    int i2 = e0 + 2 * pt;
                    float dc1 = fmaxf(fmaf(-t2v[k],
                                 fmaf(lamv[k], shIp1[c1] - x2p1i[k], x2p1i[k]), 18.0f), 0.f);
                    float dc2 = fmaxf(fmaf(-t2v[k],
                                 fmaf(lamv[k], shIp1[c2v[k]] - x2p2i[k], x2p2i[k]), 18.0f), 0.f);
                    myLoss += lamv[k] * dc1 + lmv[k] * dc2 + __logf(sv2[k]);
                    myCnt++;
                    (void)i2;
                }
            }
        }
    }

    // block reduce: warp shuffle + one smem hop
    #pragma unroll
    for (int o = 16; o; o >>= 1) {
        myLoss += __shfl_xor_sync(0xffffffffu, myLoss, o);
        myCnt  += __shfl_xor_sync(0xffffffffu, myCnt,  o);
    }
    if (lane == 0) { sred[wid] = myLoss; sredi[wid] = myCnt; }
    __syncthreads();

    // ===== Phase 3: partial store + ticket; last block reduces in parallel =====
    if (tid == 0) {
        float fs = sred[0]+sred[1]+sred[2]+sred[3]+sred[4]+sred[5]+sred[6]+sred[7];
        int   is = sredi[0]+sredi[1]+sredi[2]+sredi[3]+sredi[4]+sredi[5]+sredi[6]+sredi[7];
        g_partF[b] = fs;
        g_partI[b] = is;
        __threadfence();
        unsigned t = atomicAdd(&g_done, 1u);
        lastFlag = (t == GB - 1);
    }
    __syncthreads();
    if (lastFlag) {
        float fv = __ldcg(&g_partF[tid]);     // bypass L1 (written by other SMs)
        int   iv = __ldcg(&g_partI[tid]);
        #pragma unroll
        for (int o = 16; o; o >>= 1) {
            fv += __shfl_xor_sync(0xffffffffu, fv, o);
            iv += __shfl_xor_sync(0xffffffffu, iv, o);
        }
        if (lane == 0) { sred[wid] = fv; sredi[wid] = iv; }
        __syncthreads();
        // reset per-launch counters for graph replay (all blocks have passed
        // their use of these counters before the last ticket arrives)
        if (tid < NT) g_tileCnt[tid] = 0u;
        if (tid == NT) g_normCnt = 0u;
        if (tid == NT + 1) g_redCnt = 0u;
        if (tid == 0) {
            float fs = sred[0]+sred[1]+sred[2]+sred[3]+sred[4]+sred[5]+sred[6]+sred[7];
            int   is = sredi[0]+sredi[1]+sredi[2]+sredi[3]+sredi[4]+sredi[5]+sredi[6]+sredi[7];
            out[0] = fs / (float)(Nn + is);
            __threadfence();
            atomicExch(&g_done, 0u);          // reset for graph replay
        }
    }
}

// ---------------- entry -------------------------------------------------------
extern "C" void kernel_launch(void* const* d_in, const int* in_sizes, int n_in,
                              void* d_out, int out_size) {
    const float* X = (const float*)d_in[0];   // [256,512]
    const float* P = (const float*)d_in[1];   // [100,512]
    const int*   T = (const int*)d_in[2];     // [256]
    float* out = (float*)d_out;

    k_fused<<<GB, 256>>>(X, P, T, out);
}